// round 5
// baseline (speedup 1.0000x reference)
#include <cuda_runtime.h>
#include <cstdint>

#define NN   100000
#define NE   3200000
#define FIN  128
#define HID  16
#define ND   2000
#define FULLMASK 0xffffffffu

// ---------------- scratch (no allocs allowed) ----------------
__device__ __align__(16) float g_deg [NN];         // degree (incl self loop)
__device__ __align__(16) float g_hs  [NN * HID];   // dinv-scaled features (gather source)
__device__ __align__(16) float g_agg [NN * HID];   // aggregation (self term folded in)
__device__              unsigned char g_mask[NN];
__device__ __align__(16) int2  g_list1[NE];        // edges with mask[dst]
__device__ __align__(16) int2  g_list2[NE];        // edges with dst < ND
__device__ int g_cnt1;
__device__ int g_cnt2;
__device__ __align__(16) float g_h2  [ND * HID];
__device__ __align__(16) float g_tmp [ND * HID];

// ---------------- init ----------------
__global__ void k_init() {
    int i = blockIdx.x * 256 + threadIdx.x;
    if (i < NN) {
        g_deg[i]  = 1.0f;                 // self loop
        g_mask[i] = (i < ND) ? 1 : 0;
    }
    if (i == 0) { g_cnt1 = 0; g_cnt2 = 0; }
}

// ---------------- pass 1: degree + mask ----------------
__global__ void k_prep(const int* __restrict__ src, const int* __restrict__ dst) {
    int t = blockIdx.x * 256 + threadIdx.x;
    int base = t * 4;
    if (base >= NE) return;
    int4 d = *reinterpret_cast<const int4*>(dst + base);
    atomicAdd(g_deg + d.x, 1.0f);
    atomicAdd(g_deg + d.y, 1.0f);
    atomicAdd(g_deg + d.z, 1.0f);
    atomicAdd(g_deg + d.w, 1.0f);
    if (d.x < ND) g_mask[__ldg(src + base + 0)] = 1;
    if (d.y < ND) g_mask[__ldg(src + base + 1)] = 1;
    if (d.z < ND) g_mask[__ldg(src + base + 2)] = 1;
    if (d.w < ND) g_mask[__ldg(src + base + 3)] = 1;
}

// ---------------- pass 2: compact edge lists (warp-aggregated append) ----------------
__global__ void k_compact(const int* __restrict__ src, const int* __restrict__ dst) {
    int e = blockIdx.x * 256 + threadIdx.x;   // grid covers NE exactly
    int lane = threadIdx.x & 31;
    int s = __ldg(src + e);
    int d = __ldg(dst + e);

    bool take1 = (g_mask[d] != 0);
    unsigned b1 = __ballot_sync(FULLMASK, take1);
    if (b1) {
        int pos1 = 0;
        if (lane == __ffs(b1) - 1) pos1 = atomicAdd(&g_cnt1, __popc(b1));
        pos1 = __shfl_sync(FULLMASK, pos1, __ffs(b1) - 1);
        if (take1) g_list1[pos1 + __popc(b1 & ((1u << lane) - 1))] = make_int2(s, d);
    }

    bool take2 = (d < ND);
    unsigned b2 = __ballot_sync(FULLMASK, take2);
    if (b2) {
        int pos2 = 0;
        if (lane == __ffs(b2) - 1) pos2 = atomicAdd(&g_cnt2, __popc(b2));
        pos2 = __shfl_sync(FULLMASK, pos2, __ffs(b2) - 1);
        if (take2) g_list2[pos2 + __popc(b2 & ((1u << lane) - 1))] = make_int2(s, d);
    }
}

// ---------------- GEMM1: g_hs = g_agg = rsqrt(deg) * (x @ W1) ----------------
// One node per thread; x row loaded straight from gmem into registers (32-k chunks);
// W rows read as warp-uniform LDS.128 (broadcast). No transpose, no x staging.
__global__ void __launch_bounds__(256) k_gemm1(const float* __restrict__ x,
                                               const float* __restrict__ W1) {
    __shared__ __align__(16) float W1s[FIN * HID];   // 8 KB
    int tid = threadIdx.x;
    for (int i = tid; i < FIN * HID / 4; i += 256)
        reinterpret_cast<float4*>(W1s)[i] = reinterpret_cast<const float4*>(W1)[i];
    __syncthreads();

    int node = blockIdx.x * 256 + tid;
    bool valid = node < NN;
    const float4* xr = reinterpret_cast<const float4*>(x + (size_t)node * FIN);

    float acc[HID];
#pragma unroll
    for (int j = 0; j < HID; j++) acc[j] = 0.f;

#pragma unroll 1
    for (int c = 0; c < FIN / 32; c++) {
        float4 xc[8];
        if (valid) {
#pragma unroll
            for (int i = 0; i < 8; i++) xc[i] = __ldg(xr + c * 8 + i);
        }
#pragma unroll
        for (int i = 0; i < 8; i++) {
            float xv[4] = {xc[i].x, xc[i].y, xc[i].z, xc[i].w};
#pragma unroll
            for (int q = 0; q < 4; q++) {
                int k = c * 32 + i * 4 + q;
                const float4* wr = reinterpret_cast<const float4*>(W1s + k * HID);
                float4 w0 = wr[0], w1 = wr[1], w2 = wr[2], w3 = wr[3];
                float v = xv[q];
                acc[0]  += v * w0.x; acc[1]  += v * w0.y; acc[2]  += v * w0.z; acc[3]  += v * w0.w;
                acc[4]  += v * w1.x; acc[5]  += v * w1.y; acc[6]  += v * w1.z; acc[7]  += v * w1.w;
                acc[8]  += v * w2.x; acc[9]  += v * w2.y; acc[10] += v * w2.z; acc[11] += v * w2.w;
                acc[12] += v * w3.x; acc[13] += v * w3.y; acc[14] += v * w3.z; acc[15] += v * w3.w;
            }
        }
    }
    if (!valid) return;
    float di = rsqrtf(g_deg[node]);
#pragma unroll
    for (int q = 0; q < 4; q++) {
        float4 v = make_float4(acc[q*4+0]*di, acc[q*4+1]*di, acc[q*4+2]*di, acc[q*4+3]*di);
        *reinterpret_cast<float4*>(g_hs  + (size_t)node * HID + q * 4) = v;
        *reinterpret_cast<float4*>(g_agg + (size_t)node * HID + q * 4) = v;   // self term
    }
}

// ---------------- edge scatter over a compacted list (grid-stride, 4 lanes/edge) ----------------
__global__ void k_edge_list(const int2* __restrict__ list, const int* __restrict__ cnt_p) {
    int total = *cnt_p * 4;
    int stride = gridDim.x * 256;
    for (int i = blockIdx.x * 256 + threadIdx.x; i < total; i += stride) {
        int e = i >> 2;
        int c = (i & 3) * 4;
        int2 sd = __ldg(list + e);
        float4 v = *reinterpret_cast<const float4*>(g_hs + (size_t)sd.x * HID + c);
        float* p = g_agg + (size_t)sd.y * HID + c;
        asm volatile("red.global.add.v4.f32 [%0], {%1,%2,%3,%4};"
                     :: "l"(__cvta_generic_to_global(p)),
                        "f"(v.x), "f"(v.y), "f"(v.z), "f"(v.w)
                     : "memory");
    }
}

// ---------------- GEMM2 (masked nodes): g_hs = dinv*( relu(dinv*agg1+b1) @ W2 ) ----------------
__global__ void k_gemm2(const float* __restrict__ W2, const float* __restrict__ b1) {
    __shared__ float W2s[HID * HID];
    __shared__ float b1s[HID];
    int tid = threadIdx.x;
    W2s[tid] = W2[tid];
    if (tid < HID) b1s[tid] = b1[tid];
    __syncthreads();
    int n = blockIdx.x * 256 + tid;
    if (n >= NN || !g_mask[n]) return;

    float di = rsqrtf(g_deg[n]);
    float row[HID];
    const float4* rv = reinterpret_cast<const float4*>(g_agg + (size_t)n * HID);
#pragma unroll
    for (int q = 0; q < 4; q++) {
        float4 v = rv[q];
        row[q * 4 + 0] = fmaxf(di * v.x + b1s[q * 4 + 0], 0.f);
        row[q * 4 + 1] = fmaxf(di * v.y + b1s[q * 4 + 1], 0.f);
        row[q * 4 + 2] = fmaxf(di * v.z + b1s[q * 4 + 2], 0.f);
        row[q * 4 + 3] = fmaxf(di * v.w + b1s[q * 4 + 3], 0.f);
    }
    float4 acc[4];
#pragma unroll
    for (int q = 0; q < 4; q++) acc[q] = make_float4(0.f, 0.f, 0.f, 0.f);
#pragma unroll
    for (int k = 0; k < HID; k++) {
        float hv = row[k];
#pragma unroll
        for (int q = 0; q < 4; q++) {
            float4 w = *reinterpret_cast<const float4*>(W2s + k * HID + q * 4);
            acc[q].x += hv * w.x; acc[q].y += hv * w.y;
            acc[q].z += hv * w.z; acc[q].w += hv * w.w;
        }
    }
#pragma unroll
    for (int q = 0; q < 4; q++) {
        acc[q].x *= di; acc[q].y *= di; acc[q].z *= di; acc[q].w *= di;
        *reinterpret_cast<float4*>(g_hs + (size_t)n * HID + q * 4) = acc[q];
        if (n < ND)
            *reinterpret_cast<float4*>(g_agg + (size_t)n * HID + q * 4) = acc[q];
    }
}

// ---------------- finalize layer 2 + tmp = h2 @ P ----------------
__global__ void k_pred1(const float* __restrict__ P, const float* __restrict__ b2) {
    __shared__ float Ps[HID * HID];
    __shared__ float h2s[16][17];
    int tid = threadIdx.x;
    Ps[tid] = P[tid];
    int gid = blockIdx.x * 256 + tid;      // < ND*HID
    int i = gid >> 4, j = gid & 15;
    int il = tid >> 4, jl = tid & 15;
    float v = rsqrtf(g_deg[i]) * g_agg[gid] + __ldg(b2 + j);
    g_h2[gid] = v;
    h2s[il][jl] = v;
    __syncthreads();
    float acc = 0.f;
#pragma unroll
    for (int k = 0; k < HID; k++) acc += h2s[il][k] * Ps[k * HID + j];
    g_tmp[gid] = acc;
}

// ---------------- out: 32x32 tile / block, 2x2 per thread (bounds-guarded: ND % 32 != 0) ----------------
__global__ void k_out(float* __restrict__ out) {
    __shared__ float ts[32][17];
    __shared__ float hs[32][17];
    int tid = threadIdx.x;
    int ib = blockIdx.y * 32, jb = blockIdx.x * 32;
    {
        int r = tid >> 3;             // 0..31
        int c2 = (tid & 7) * 2;       // 0,2,..14
        float2 tv = (ib + r < ND)
            ? *reinterpret_cast<const float2*>(g_tmp + (size_t)(ib + r) * HID + c2)
            : make_float2(0.f, 0.f);
        float2 hv = (jb + r < ND)
            ? *reinterpret_cast<const float2*>(g_h2 + (size_t)(jb + r) * HID + c2)
            : make_float2(0.f, 0.f);
        ts[r][c2] = tv.x; ts[r][c2 + 1] = tv.y;
        hs[r][c2] = hv.x; hs[r][c2 + 1] = hv.y;
    }
    __syncthreads();
    int ty = tid >> 4, tx = tid & 15;
    float a00 = 0.f, a01 = 0.f, a10 = 0.f, a11 = 0.f;
#pragma unroll
    for (int k = 0; k < HID; k++) {
        float t0 = ts[ty][k], t1 = ts[ty + 16][k];
        float h0 = hs[tx][k], h1 = hs[tx + 16][k];
        a00 += t0 * h0; a01 += t0 * h1;
        a10 += t1 * h0; a11 += t1 * h1;
    }
    int i0 = ib + ty, i1 = ib + ty + 16;
    int j0 = jb + tx, j1 = jb + tx + 16;
    if (i0 < ND) {
        if (j0 < ND) out[(size_t)i0 * ND + j0] = a00;
        if (j1 < ND) out[(size_t)i0 * ND + j1] = a01;
    }
    if (i1 < ND) {
        if (j0 < ND) out[(size_t)i1 * ND + j0] = a10;
        if (j1 < ND) out[(size_t)i1 * ND + j1] = a11;
    }
}

// ---------------- launch ----------------
extern "C" void kernel_launch(void* const* d_in, const int* in_sizes, int n_in,
                              void* d_out, int out_size) {
    (void)in_sizes; (void)n_in; (void)out_size;
    const float* x  = (const float*)d_in[0];
    const int*   ei = (const int*)  d_in[1];
    const float* W1 = (const float*)d_in[2];
    const float* b1 = (const float*)d_in[3];
    const float* W2 = (const float*)d_in[4];
    const float* b2 = (const float*)d_in[5];
    const float* P  = (const float*)d_in[6];
    float* out = (float*)d_out;

    const int* src = ei;
    const int* dst = ei + NE;

    int* cnt1_p; cudaGetSymbolAddress((void**)&cnt1_p, g_cnt1);
    int* cnt2_p; cudaGetSymbolAddress((void**)&cnt2_p, g_cnt2);
    int2* l1_p;  cudaGetSymbolAddress((void**)&l1_p, g_list1);
    int2* l2_p;  cudaGetSymbolAddress((void**)&l2_p, g_list2);

    k_init   <<<(NN + 255) / 256, 256>>>();
    k_prep   <<<NE / 4 / 256, 256>>>(src, dst);
    k_compact<<<NE / 256, 256>>>(src, dst);

    // layer 1
    k_gemm1    <<<(NN + 255) / 256, 256>>>(x, W1);
    k_edge_list<<<1184, 256>>>(l1_p, cnt1_p);

    // layer 2
    k_gemm2    <<<(NN + 255) / 256, 256>>>(W2, b1);
    k_edge_list<<<592, 256>>>(l2_p, cnt2_p);

    // decoder
    k_pred1<<<(ND * HID) / 256, 256>>>(P, b2);
    k_out  <<<dim3((ND + 31) / 32, (ND + 31) / 32), 256>>>(out);
}

// round 6
// speedup vs baseline: 1.1960x; 1.1960x over previous
#include <cuda_runtime.h>
#include <cstdint>

#define NN   100000
#define NE   3200000
#define FIN  128
#define HID  16
#define ND   2000
#define BMW  3125            // bitmask words = ceil(NN/32)
#define FULLMASK 0xffffffffu

// ---------------- scratch (no allocs allowed) ----------------
__device__ __align__(16) float    g_deg [NN];        // degree (incl self loop)
__device__ __align__(16) float    g_hs  [NN * HID];  // dinv-scaled features (gather source)
__device__ __align__(16) float    g_agg [NN * HID];  // aggregation (self term folded in)
__device__ __align__(16) unsigned g_bm  [BMW];       // node mask bitset
__device__ __align__(16) int2     g_list2[NE / 8];   // edges with dst < ND (expect ~64k)
__device__ int g_cnt2;
__device__ __align__(16) float    g_h2  [ND * HID];
__device__ __align__(16) float    g_tmp [ND * HID];

// ---------------- f32x2 helpers ----------------
__device__ __forceinline__ unsigned long long pack2(float v) {
    unsigned long long r;
    unsigned u = __float_as_uint(v);
    asm("mov.b64 %0, {%1, %1};" : "=l"(r) : "r"(u));
    return r;
}
__device__ __forceinline__ unsigned long long ffma2(unsigned long long a,
                                                    unsigned long long b,
                                                    unsigned long long c) {
    unsigned long long d;
    asm("fma.rn.f32x2 %0, %1, %2, %3;" : "=l"(d) : "l"(a), "l"(b), "l"(c));
    return d;
}
__device__ __forceinline__ float2 unpack2(unsigned long long v) {
    unsigned lo, hi;
    asm("mov.b64 {%0, %1}, %2;" : "=r"(lo), "=r"(hi) : "l"(v));
    return make_float2(__uint_as_float(lo), __uint_as_float(hi));
}

// ---------------- init: deg=1, bm = (n < ND), cnt2 = 0 ----------------
__global__ void k_init() {
    int i = blockIdx.x * 256 + threadIdx.x;
    if (i < NN) g_deg[i] = 1.0f;                     // self loop
    if (i < BMW) g_bm[i] = (i < 62) ? ~0u : ((i == 62) ? 0x0000FFFFu : 0u);
    if (i == 0) g_cnt2 = 0;
}

// ---------------- prep: degree + mask bits + drug-edge list ----------------
__global__ void k_prep(const int* __restrict__ src, const int* __restrict__ dst) {
    int e = blockIdx.x * 256 + threadIdx.x;          // grid covers NE exactly
    int lane = threadIdx.x & 31;
    int d = __ldg(dst + e);
    atomicAdd(g_deg + d, 1.0f);

    bool take2 = (d < ND);
    int s = 0;
    if (take2) {
        s = __ldg(src + e);
        atomicOr(g_bm + (s >> 5), 1u << (s & 31));
    }
    unsigned b2 = __ballot_sync(FULLMASK, take2);
    if (b2) {
        int leader = __ffs(b2) - 1;
        int pos = 0;
        if (lane == leader) pos = atomicAdd(&g_cnt2, __popc(b2));
        pos = __shfl_sync(FULLMASK, pos, leader);
        if (take2) g_list2[pos + __popc(b2 & ((1u << lane) - 1))] = make_int2(s, d);
    }
}

// ---------------- GEMM1: g_hs = g_agg = rsqrt(deg) * (x @ W1) ----------------
// 1 thread = 1 node. x staged coalesced in smem (32-k chunks, row stride 36 floats:
// conflict-free STS.128 and per-thread LDS.128). W read warp-uniform (broadcast).
// Inner product uses packed fma.rn.f32x2 (8 FFMA2 per k).
__global__ void __launch_bounds__(256) k_gemm1(const float* __restrict__ x,
                                               const float* __restrict__ W1) {
    __shared__ __align__(16) float W1s[FIN * HID];   // 8 KB
    __shared__ __align__(16) float xs[256 * 36];     // 36 KB
    int tid = threadIdx.x;
    int nbase = blockIdx.x * 256;
    int node = nbase + tid;

    for (int i = tid; i < FIN * HID / 4; i += 256)
        reinterpret_cast<float4*>(W1s)[i] = reinterpret_cast<const float4*>(W1)[i];

    unsigned long long acc2[8];
#pragma unroll
    for (int j = 0; j < 8; j++) acc2[j] = 0ull;

#pragma unroll 1
    for (int c = 0; c < 4; c++) {
        __syncthreads();
#pragma unroll
        for (int it = 0; it < 8; it++) {
            int i = tid + it * 256;          // 0..2047
            int row = i >> 3, f4 = i & 7;
            if (nbase + row < NN) {
                float4 v = *reinterpret_cast<const float4*>(
                    x + (size_t)(nbase + row) * FIN + c * 32 + f4 * 4);
                *reinterpret_cast<float4*>(xs + row * 36 + f4 * 4) = v;
            }
        }
        __syncthreads();
#pragma unroll
        for (int k4 = 0; k4 < 8; k4++) {
            float4 xv4 = *reinterpret_cast<const float4*>(xs + tid * 36 + k4 * 4);
            float xv[4] = {xv4.x, xv4.y, xv4.z, xv4.w};
#pragma unroll
            for (int q = 0; q < 4; q++) {
                int k = c * 32 + k4 * 4 + q;
                const ulonglong2* wr = reinterpret_cast<const ulonglong2*>(W1s + k * HID);
                ulonglong2 wa = wr[0], wb = wr[1];
                unsigned long long xv2 = pack2(xv[q]);
                acc2[0] = ffma2(xv2, wa.x, acc2[0]);
                acc2[1] = ffma2(xv2, wa.y, acc2[1]);
                acc2[2] = ffma2(xv2, wb.x, acc2[2]);
                acc2[3] = ffma2(xv2, wb.y, acc2[3]);
                ulonglong2 wc = wr[2], wd = wr[3];
                acc2[4] = ffma2(xv2, wc.x, acc2[4]);
                acc2[5] = ffma2(xv2, wc.y, acc2[5]);
                acc2[6] = ffma2(xv2, wd.x, acc2[6]);
                acc2[7] = ffma2(xv2, wd.y, acc2[7]);
            }
        }
    }
    if (node >= NN) return;
    float di = rsqrtf(g_deg[node]);
#pragma unroll
    for (int q = 0; q < 4; q++) {
        float2 a = unpack2(acc2[q * 2]);
        float2 b = unpack2(acc2[q * 2 + 1]);
        float4 v = make_float4(a.x * di, a.y * di, b.x * di, b.y * di);
        *reinterpret_cast<float4*>(g_hs  + (size_t)node * HID + q * 4) = v;
        *reinterpret_cast<float4*>(g_agg + (size_t)node * HID + q * 4) = v;   // self term
    }
}

// ---------------- edge pass 1: all edges, smem bitmask test, 4 lanes/edge ----------------
__global__ void k_edge1(const int* __restrict__ src, const int* __restrict__ dst) {
    __shared__ unsigned bm[BMW];
    for (int i = threadIdx.x; i < BMW; i += 256) bm[i] = g_bm[i];
    __syncthreads();
    const int total = NE * 4;
    const int stride = gridDim.x * 256;
    for (int i = blockIdx.x * 256 + threadIdx.x; i < total; i += stride) {
        int e = i >> 2;
        int d = __ldg(dst + e);
        if (!((bm[d >> 5] >> (d & 31)) & 1)) continue;
        int c = (i & 3) * 4;
        int s = __ldg(src + e);
        float4 v = *reinterpret_cast<const float4*>(g_hs + (size_t)s * HID + c);
        float* p = g_agg + (size_t)d * HID + c;
        asm volatile("red.global.add.v4.f32 [%0], {%1,%2,%3,%4};"
                     :: "l"(__cvta_generic_to_global(p)),
                        "f"(v.x), "f"(v.y), "f"(v.z), "f"(v.w)
                     : "memory");
    }
}

// ---------------- edge pass 2: compacted drug-edge list ----------------
__global__ void k_edge2() {
    int total = g_cnt2 * 4;
    const int stride = gridDim.x * 256;
    for (int i = blockIdx.x * 256 + threadIdx.x; i < total; i += stride) {
        int e = i >> 2;
        int c = (i & 3) * 4;
        int2 sd = __ldg(&g_list2[e]);
        float4 v = *reinterpret_cast<const float4*>(g_hs + (size_t)sd.x * HID + c);
        float* p = g_agg + (size_t)sd.y * HID + c;
        asm volatile("red.global.add.v4.f32 [%0], {%1,%2,%3,%4};"
                     :: "l"(__cvta_generic_to_global(p)),
                        "f"(v.x), "f"(v.y), "f"(v.z), "f"(v.w)
                     : "memory");
    }
}

// ---------------- GEMM2 (masked nodes): g_hs = dinv*( relu(dinv*agg1+b1) @ W2 ) ----------------
__global__ void k_gemm2(const float* __restrict__ W2, const float* __restrict__ b1) {
    __shared__ float W2s[HID * HID];
    __shared__ float b1s[HID];
    int tid = threadIdx.x;
    W2s[tid] = W2[tid];
    if (tid < HID) b1s[tid] = b1[tid];
    __syncthreads();
    int n = blockIdx.x * 256 + tid;
    if (n >= NN) return;
    if (!((g_bm[n >> 5] >> (n & 31)) & 1)) return;

    float di = rsqrtf(g_deg[n]);
    float row[HID];
    const float4* rv = reinterpret_cast<const float4*>(g_agg + (size_t)n * HID);
#pragma unroll
    for (int q = 0; q < 4; q++) {
        float4 v = rv[q];
        row[q * 4 + 0] = fmaxf(di * v.x + b1s[q * 4 + 0], 0.f);
        row[q * 4 + 1] = fmaxf(di * v.y + b1s[q * 4 + 1], 0.f);
        row[q * 4 + 2] = fmaxf(di * v.z + b1s[q * 4 + 2], 0.f);
        row[q * 4 + 3] = fmaxf(di * v.w + b1s[q * 4 + 3], 0.f);
    }
    float4 acc[4];
#pragma unroll
    for (int q = 0; q < 4; q++) acc[q] = make_float4(0.f, 0.f, 0.f, 0.f);
#pragma unroll
    for (int k = 0; k < HID; k++) {
        float hv = row[k];
#pragma unroll
        for (int q = 0; q < 4; q++) {
            float4 w = *reinterpret_cast<const float4*>(W2s + k * HID + q * 4);
            acc[q].x += hv * w.x; acc[q].y += hv * w.y;
            acc[q].z += hv * w.z; acc[q].w += hv * w.w;
        }
    }
#pragma unroll
    for (int q = 0; q < 4; q++) {
        acc[q].x *= di; acc[q].y *= di; acc[q].z *= di; acc[q].w *= di;
        *reinterpret_cast<float4*>(g_hs + (size_t)n * HID + q * 4) = acc[q];
        if (n < ND)
            *reinterpret_cast<float4*>(g_agg + (size_t)n * HID + q * 4) = acc[q];   // self term
    }
}

// ---------------- finalize layer 2 + tmp = h2 @ P ----------------
__global__ void k_pred1(const float* __restrict__ P, const float* __restrict__ b2) {
    __shared__ float Ps[HID * HID];
    __shared__ float h2s[16][17];
    int tid = threadIdx.x;
    Ps[tid] = P[tid];
    int gid = blockIdx.x * 256 + tid;      // < ND*HID
    int i = gid >> 4, j = gid & 15;
    int il = tid >> 4, jl = tid & 15;
    float v = rsqrtf(g_deg[i]) * g_agg[gid] + __ldg(b2 + j);
    g_h2[gid] = v;
    h2s[il][jl] = v;
    __syncthreads();
    float acc = 0.f;
#pragma unroll
    for (int k = 0; k < HID; k++) acc += h2s[il][k] * Ps[k * HID + j];
    g_tmp[gid] = acc;
}

// ---------------- out: 32x32 tile / block, 2x2 per thread (bounds-guarded) ----------------
__global__ void k_out(float* __restrict__ out) {
    __shared__ float ts[32][17];
    __shared__ float hs[32][17];
    int tid = threadIdx.x;
    int ib = blockIdx.y * 32, jb = blockIdx.x * 32;
    {
        int r = tid >> 3;             // 0..31
        int c2 = (tid & 7) * 2;       // 0,2,..14
        float2 tv = (ib + r < ND)
            ? *reinterpret_cast<const float2*>(g_tmp + (size_t)(ib + r) * HID + c2)
            : make_float2(0.f, 0.f);
        float2 hv = (jb + r < ND)
            ? *reinterpret_cast<const float2*>(g_h2 + (size_t)(jb + r) * HID + c2)
            : make_float2(0.f, 0.f);
        ts[r][c2] = tv.x; ts[r][c2 + 1] = tv.y;
        hs[r][c2] = hv.x; hs[r][c2 + 1] = hv.y;
    }
    __syncthreads();
    int ty = tid >> 4, tx = tid & 15;
    float a00 = 0.f, a01 = 0.f, a10 = 0.f, a11 = 0.f;
#pragma unroll
    for (int k = 0; k < HID; k++) {
        float t0 = ts[ty][k], t1 = ts[ty + 16][k];
        float h0 = hs[tx][k], h1 = hs[tx + 16][k];
        a00 += t0 * h0; a01 += t0 * h1;
        a10 += t1 * h0; a11 += t1 * h1;
    }
    int i0 = ib + ty, i1 = ib + ty + 16;
    int j0 = jb + tx, j1 = jb + tx + 16;
    if (i0 < ND) {
        if (j0 < ND) out[(size_t)i0 * ND + j0] = a00;
        if (j1 < ND) out[(size_t)i0 * ND + j1] = a01;
    }
    if (i1 < ND) {
        if (j0 < ND) out[(size_t)i1 * ND + j0] = a10;
        if (j1 < ND) out[(size_t)i1 * ND + j1] = a11;
    }
}

// ---------------- launch ----------------
extern "C" void kernel_launch(void* const* d_in, const int* in_sizes, int n_in,
                              void* d_out, int out_size) {
    (void)in_sizes; (void)n_in; (void)out_size;
    const float* x  = (const float*)d_in[0];
    const int*   ei = (const int*)  d_in[1];
    const float* W1 = (const float*)d_in[2];
    const float* b1 = (const float*)d_in[3];
    const float* W2 = (const float*)d_in[4];
    const float* b2 = (const float*)d_in[5];
    const float* P  = (const float*)d_in[6];
    float* out = (float*)d_out;

    const int* src = ei;
    const int* dst = ei + NE;

    k_init<<<(NN + 255) / 256, 256>>>();
    k_prep<<<NE / 256, 256>>>(src, dst);

    // layer 1
    k_gemm1<<<(NN + 255) / 256, 256>>>(x, W1);
    k_edge1<<<1184, 256>>>(src, dst);

    // layer 2
    k_gemm2<<<(NN + 255) / 256, 256>>>(W2, b1);
    k_edge2<<<256, 256>>>();

    // decoder
    k_pred1<<<(ND * HID) / 256, 256>>>(P, b2);
    k_out  <<<dim3((ND + 31) / 32, (ND + 31) / 32), 256>>>(out);
}